// round 3
// baseline (speedup 1.0000x reference)
#include <cuda_runtime.h>
#include <math.h>

// Problem constants
static constexpr int BB  = 4096;
static constexpr int D3  = 288;
static constexpr int LZ  = 32;
static constexpr int HH  = 512;
static constexpr int OO  = 96;
static constexpr int EE  = 8;
static constexpr int GHD = 128;

static constexpr int IN0 = D3 + LZ;   // 320
static constexpr int IN1 = HH + LZ;   // 544

// Scratch (no allocations allowed -> __device__ globals)
__device__ float d_hcat0[BB * IN0];
__device__ float d_hcat1[BB * IN1];
__device__ float d_hcat2[BB * IN1];
__device__ float d_h3[BB * HH];
__device__ float d_gh1[BB * GHD];
__device__ float d_gh2[BB * GHD];
__device__ float d_gate[BB * EE];

// ---- packed fp32x2 helpers (sm_103a: FFMA-3reg is half-rate; f32x2 restores full rate) ----
__device__ __forceinline__ void fma2(unsigned long long& d, unsigned long long a, unsigned long long b) {
    asm("fma.rn.f32x2 %0, %1, %2, %0;" : "+l"(d) : "l"(a), "l"(b));
}
__device__ __forceinline__ unsigned long long pack2(float lo, float hi) {
    unsigned long long r;
    asm("mov.b64 %0, {%1, %2};" : "=l"(r) : "f"(lo), "f"(hi));
    return r;
}
__device__ __forceinline__ float2 unpack2(unsigned long long v) {
    float2 f;
    asm("mov.b64 {%0, %1}, %2;" : "=f"(f.x), "=f"(f.y) : "l"(v));
    return f;
}
__device__ __forceinline__ float elu1(float x) { return x > 0.f ? x : expm1f(x); }

// ---- input packing: hcat0 = [x|z], and write z tails of hcat1/hcat2 once ----
__global__ void pack_kernel(const float* __restrict__ x, const float* __restrict__ z) {
    int idx = blockIdx.x * blockDim.x + threadIdx.x;
    if (idx < BB * IN0) {
        int b = idx / IN0, c = idx % IN0;
        d_hcat0[idx] = (c < D3) ? x[b * D3 + c] : z[b * LZ + (c - D3)];
    }
    if (idx < BB * LZ) {
        int b = idx / LZ;
        int c = idx % LZ;
        float zv = z[idx];
        d_hcat1[b * IN1 + HH + c] = zv;
        d_hcat2[b * IN1 + HH + c] = zv;
    }
}

// ---- blended expert GEMM ----
// C[b,o] = act( sum_e g[b,e] * ( sum_i A[b,i] * W[e,o,i] + bias[e,o] ) )
// GATE=false => E==1 plain linear with bias.
// Tiling: BM x 64 output tile, BK=16, 256 threads, thread tile TM x 4.
// M-dim paired into f32x2; W stored in smem pre-duplicated {w,w}.
template <int BM, int E, bool GATE, bool ACT>
__global__ void __launch_bounds__(256, 2) blended_gemm(
    const float* __restrict__ A, int lda,
    const float* __restrict__ W, const float* __restrict__ bias,
    const float* __restrict__ g,
    float* __restrict__ C, int ldc, int Nout, int Kin)
{
    constexpr int BN = 64, BK = 16;
    constexpr int TM  = BM / 16;   // 8 (BM=128) or 4 (BM=64)
    constexpr int TM2 = TM / 2;
    constexpr int TN  = 4;

    extern __shared__ char smraw[];
    float* As = (float*)smraw;                                             // [BK][BM]
    unsigned long long* Bs = (unsigned long long*)(smraw + BK * BM * 4);   // [E][BK][BN], dup pairs
    float* Gs = (float*)(smraw + BK * BM * 4 + (size_t)E * BK * BN * 8);   // [BM][E] (GATE only)

    const int tid = threadIdx.x;
    const int tx = tid & 15;
    const int ty = tid >> 4;
    const int m0 = blockIdx.y * BM;
    const int n0 = blockIdx.x * BN;
    const int mb = ty * TM;
    const int nb = tx * TN;

    if (GATE) {
        for (int i = tid; i < BM * E / 4; i += 256)
            ((float4*)Gs)[i] = ((const float4*)(g + (size_t)m0 * E))[i];
    }

    unsigned long long acc[TM2][TN];
#pragma unroll
    for (int i = 0; i < TM2; i++)
#pragma unroll
        for (int j = 0; j < TN; j++) acc[i][j] = 0ull;

    const int ktiles = Kin / BK;
    for (int kt = 0; kt < ktiles; kt++) {
        const int k0 = kt * BK;
        __syncthreads();
        // stage A tile (transposed to [k][m])
        for (int i = tid; i < BM * 4; i += 256) {
            int r = i >> 2, c4 = i & 3;
            float4 v = *(const float4*)(A + (size_t)(m0 + r) * lda + k0 + c4 * 4);
            int kk = c4 * 4;
            As[(kk + 0) * BM + r] = v.x;
            As[(kk + 1) * BM + r] = v.y;
            As[(kk + 2) * BM + r] = v.z;
            As[(kk + 3) * BM + r] = v.w;
        }
        // stage W tile, duplicated into 64-bit {w,w} pairs
        for (int i = tid; i < E * 256; i += 256) {
            int e = i >> 8;
            int rem = i & 255;
            int n = rem >> 2, c4 = rem & 3;
            float4 v = make_float4(0.f, 0.f, 0.f, 0.f);
            if (n0 + n < Nout)
                v = *(const float4*)(W + ((size_t)e * Nout + n0 + n) * Kin + k0 + c4 * 4);
            int kk = c4 * 4;
            unsigned long long* bp = Bs + ((size_t)e * BK) * BN + n;
            bp[(kk + 0) * BN] = pack2(v.x, v.x);
            bp[(kk + 1) * BN] = pack2(v.y, v.y);
            bp[(kk + 2) * BN] = pack2(v.z, v.z);
            bp[(kk + 3) * BN] = pack2(v.w, v.w);
        }
        __syncthreads();

#pragma unroll 1
        for (int e = 0; e < E; e++) {
            if (GATE) {
                unsigned long long part[TM2][TN];
#pragma unroll
                for (int i = 0; i < TM2; i++)
#pragma unroll
                    for (int j = 0; j < TN; j++) part[i][j] = 0ull;
#pragma unroll
                for (int k = 0; k < BK; k++) {
                    unsigned long long areg[TM2];
#pragma unroll
                    for (int i = 0; i < TM2 / 2; i++) {
                        ulonglong2 t = *(const ulonglong2*)(As + k * BM + mb + i * 4);
                        areg[2 * i]     = t.x;
                        areg[2 * i + 1] = t.y;
                    }
                    unsigned long long breg[TN];
#pragma unroll
                    for (int j = 0; j < TN / 2; j++) {
                        ulonglong2 t = *(const ulonglong2*)(Bs + ((size_t)e * BK + k) * BN + nb + j * 2);
                        breg[2 * j]     = t.x;
                        breg[2 * j + 1] = t.y;
                    }
#pragma unroll
                    for (int i = 0; i < TM2; i++)
#pragma unroll
                        for (int j = 0; j < TN; j++) fma2(part[i][j], areg[i], breg[j]);
                }
                // acc += g[b,e] * part   (per-row gate packed per M-pair)
#pragma unroll
                for (int i = 0; i < TM2; i++) {
                    unsigned long long gg =
                        pack2(Gs[(mb + 2 * i) * E + e], Gs[(mb + 2 * i + 1) * E + e]);
#pragma unroll
                    for (int j = 0; j < TN; j++) fma2(acc[i][j], gg, part[i][j]);
                }
            } else {
#pragma unroll
                for (int k = 0; k < BK; k++) {
                    unsigned long long areg[TM2];
#pragma unroll
                    for (int i = 0; i < TM2 / 2; i++) {
                        ulonglong2 t = *(const ulonglong2*)(As + k * BM + mb + i * 4);
                        areg[2 * i]     = t.x;
                        areg[2 * i + 1] = t.y;
                    }
                    unsigned long long breg[TN];
#pragma unroll
                    for (int j = 0; j < TN / 2; j++) {
                        ulonglong2 t = *(const ulonglong2*)(Bs + ((size_t)e * BK + k) * BN + nb + j * 2);
                        breg[2 * j]     = t.x;
                        breg[2 * j + 1] = t.y;
                    }
#pragma unroll
                    for (int i = 0; i < TM2; i++)
#pragma unroll
                        for (int j = 0; j < TN; j++) fma2(acc[i][j], areg[i], breg[j]);
                }
            }
        }
    }

    // epilogue: blended bias + activation
#pragma unroll
    for (int i = 0; i < TM2; i++) {
        int r0 = m0 + mb + 2 * i;
#pragma unroll
        for (int j = 0; j < TN; j++) {
            int o = n0 + nb + j;
            if (o < Nout) {
                float2 v = unpack2(acc[i][j]);
                if (GATE) {
                    float s0 = 0.f, s1 = 0.f;
#pragma unroll
                    for (int e = 0; e < E; e++) {
                        float bb = bias[e * Nout + o];
                        s0 += Gs[(mb + 2 * i) * E + e] * bb;
                        s1 += Gs[(mb + 2 * i + 1) * E + e] * bb;
                    }
                    v.x += s0; v.y += s1;
                } else {
                    float bb = bias[o];
                    v.x += bb; v.y += bb;
                }
                if (ACT) { v.x = elu1(v.x); v.y = elu1(v.y); }
                C[(size_t)r0 * ldc + o]       = v.x;
                C[(size_t)(r0 + 1) * ldc + o] = v.y;
            }
        }
    }
}

// ---- gating logits + softmax over E=8 (one thread per (row, expert)) ----
__global__ void logits_softmax(const float* __restrict__ h2,
                               const float* __restrict__ gW3,
                               const float* __restrict__ gb3) {
    int tid = blockIdx.x * blockDim.x + threadIdx.x;
    int row = tid >> 3;
    int e = tid & 7;
    if (row >= BB) return;
    float s = gb3[e];
    const float* hr = h2 + (size_t)row * GHD;
    const float* wr = gW3 + (size_t)e * GHD;
#pragma unroll 8
    for (int i = 0; i < GHD; i++) s += hr[i] * wr[i];
    // softmax within groups of 8 lanes (shfl_xor 1/2/4 stays in group)
    float m = s;
#pragma unroll
    for (int o = 4; o; o >>= 1) m = fmaxf(m, __shfl_xor_sync(0xffffffffu, m, o));
    float ex = expf(s - m);
    float sum = ex;
#pragma unroll
    for (int o = 4; o; o >>= 1) sum += __shfl_xor_sync(0xffffffffu, sum, o);
    d_gate[tid] = ex / sum;
}

extern "C" void kernel_launch(void* const* d_in, const int* in_sizes, int n_in,
                              void* d_out, int out_size) {
    const float* x   = (const float*)d_in[0];
    const float* z   = (const float*)d_in[1];
    const float* W0  = (const float*)d_in[2];
    const float* b0  = (const float*)d_in[3];
    const float* W1  = (const float*)d_in[4];
    const float* b1  = (const float*)d_in[5];
    const float* W2  = (const float*)d_in[6];
    const float* b2  = (const float*)d_in[7];
    const float* W3  = (const float*)d_in[8];
    const float* b3  = (const float*)d_in[9];
    const float* gW1 = (const float*)d_in[10];
    const float* gb1 = (const float*)d_in[11];
    const float* gW2 = (const float*)d_in[12];
    const float* gb2 = (const float*)d_in[13];
    const float* gW3 = (const float*)d_in[14];
    const float* gb3 = (const float*)d_in[15];
    float* out = (float*)d_out;
    (void)in_sizes; (void)n_in; (void)out_size;

    float *hcat0, *hcat1, *hcat2, *h3, *gh1, *gh2, *gate;
    cudaGetSymbolAddress((void**)&hcat0, d_hcat0);
    cudaGetSymbolAddress((void**)&hcat1, d_hcat1);
    cudaGetSymbolAddress((void**)&hcat2, d_hcat2);
    cudaGetSymbolAddress((void**)&h3,    d_h3);
    cudaGetSymbolAddress((void**)&gh1,   d_gh1);
    cudaGetSymbolAddress((void**)&gh2,   d_gh2);
    cudaGetSymbolAddress((void**)&gate,  d_gate);

    // dynamic smem sizes
    constexpr int SM_128_8 = 16 * 128 * 4 + 8 * 16 * 64 * 8 + 128 * 8 * 4;  // 77824
    constexpr int SM_64_8  = 16 * 64 * 4  + 8 * 16 * 64 * 8 + 64 * 8 * 4;   // 71680
    constexpr int SM_128_1 = 16 * 128 * 4 + 1 * 16 * 64 * 8;                // 16384

    cudaFuncSetAttribute(blended_gemm<128, 8, true, true>,
                         cudaFuncAttributeMaxDynamicSharedMemorySize, SM_128_8);
    cudaFuncSetAttribute(blended_gemm<64, 8, true, false>,
                         cudaFuncAttributeMaxDynamicSharedMemorySize, SM_64_8);

    // 1. pack [x|z] and z-tails
    pack_kernel<<<(BB * IN0 + 255) / 256, 256>>>(x, z);

    // 2. gating MLP
    blended_gemm<128, 1, false, true><<<dim3(2, 32), 256, SM_128_1>>>(
        hcat0, IN0, gW1, gb1, nullptr, gh1, GHD, GHD, IN0);
    blended_gemm<128, 1, false, true><<<dim3(2, 32), 256, SM_128_1>>>(
        gh1, GHD, gW2, gb2, nullptr, gh2, GHD, GHD, GHD);
    logits_softmax<<<BB * EE / 256, 256>>>(gh2, gW3, gb3);

    // 3. blended expert layers
    blended_gemm<128, 8, true, true><<<dim3(8, 32), 256, SM_128_8>>>(
        hcat0, IN0, W0, b0, gate, hcat1, IN1, HH, IN0);
    blended_gemm<128, 8, true, true><<<dim3(8, 32), 256, SM_128_8>>>(
        hcat1, IN1, W1, b1, gate, hcat2, IN1, HH, IN1);
    blended_gemm<128, 8, true, true><<<dim3(8, 32), 256, SM_128_8>>>(
        hcat2, IN1, W2, b2, gate, h3, HH, HH, IN1);
    blended_gemm<64, 8, true, false><<<dim3(2, 64), 256, SM_64_8>>>(
        h3, HH, W3, b3, gate, out, OO, OO, HH);
}

// round 5
// speedup vs baseline: 8.3397x; 8.3397x over previous
#include <cuda_runtime.h>
#include <cuda_fp16.h>
#include <math.h>
#include <stdint.h>

// ---------------- problem constants ----------------
static constexpr int BB=4096, D3=288, LZ=32, HH=512, OO=96, EE=8, GHD=128;
static constexpr int MBK = BB/128;   // 32 m-blocks

#define SWZ(o) ((o) ^ (((o) >> 3) & 0x70))

// ---------------- global scratch (pre-swizzled SW128 blobs; no allocs allowed) ----------------
// A blobs: [mblk][kblk] tiles of 128 rows x 64 half cols = 8192 halves = 16KB
// W blobs: [e][nblk][kblk] tiles of 64 rows x 64 half cols = 4096 halves = 8KB
__device__ __align__(128) __half g_A0h[MBK*5*8192], g_A0l[MBK*5*8192];
__device__ __align__(128) __half g_A1h[MBK*9*8192], g_A1l[MBK*9*8192];
__device__ __align__(128) __half g_A2h[MBK*9*8192], g_A2l[MBK*9*8192];
__device__ __align__(128) __half g_A3h[MBK*8*8192], g_A3l[MBK*8*8192];
__device__ __align__(128) __half g_G1h[MBK*2*8192], g_G1l[MBK*2*8192];
__device__ __align__(128) __half g_W0h[8*8*5*4096], g_W0l[8*8*5*4096];
__device__ __align__(128) __half g_W1h[8*8*9*4096], g_W1l[8*8*9*4096];
__device__ __align__(128) __half g_W2h[8*8*9*4096], g_W2l[8*8*9*4096];
__device__ __align__(128) __half g_W3h[8*2*8*4096], g_W3l[8*2*8*4096];
__device__ __align__(128) __half g_gW1h[2*5*4096],  g_gW1l[2*5*4096];
__device__ __align__(128) __half g_gW2h[2*2*4096],  g_gW2l[2*2*4096];
__device__ float g_gh2[BB*GHD];
__device__ float g_gate[BB*EE];

// ---------------- PTX helpers ----------------
__device__ __forceinline__ uint32_t smem_u32(const void* p) {
    uint32_t a;
    asm("{ .reg .u64 t; cvta.to.shared.u64 t, %1; cvt.u32.u64 %0, t; }" : "=r"(a) : "l"(p));
    return a;
}
__device__ __forceinline__ void mbar_init(uint32_t m, uint32_t c) {
    asm volatile("mbarrier.init.shared.b64 [%0], %1;" :: "r"(m), "r"(c) : "memory");
}
__device__ __forceinline__ void mbar_expect(uint32_t m, uint32_t b) {
    asm volatile("mbarrier.arrive.expect_tx.shared.b64 _, [%0], %1;" :: "r"(m), "r"(b) : "memory");
}
__device__ __forceinline__ void mbar_arrive(uint32_t m) {
    asm volatile("mbarrier.arrive.shared.b64 _, [%0];" :: "r"(m) : "memory");
}
__device__ __forceinline__ void mbar_wait(uint32_t m, uint32_t ph) {
    uint32_t done;
    asm volatile("{\n\t.reg .pred p;\n\t"
        "mbarrier.try_wait.parity.acquire.cta.shared::cta.b64 p, [%1], %2;\n\t"
        "selp.b32 %0, 1, 0, p;\n\t}" : "=r"(done) : "r"(m), "r"(ph) : "memory");
    while (!done) {
        asm volatile("{\n\t.reg .pred p;\n\t"
            "mbarrier.try_wait.parity.acquire.cta.shared::cta.b64 p, [%1], %2, 0x989680;\n\t"
            "selp.b32 %0, 1, 0, p;\n\t}" : "=r"(done) : "r"(m), "r"(ph) : "memory");
    }
}
__device__ __forceinline__ void bulk_g2s(uint32_t dst, const void* src, uint32_t bytes, uint32_t mbar) {
    asm volatile("cp.async.bulk.shared::cluster.global.mbarrier::complete_tx::bytes [%0], [%1], %2, [%3];"
        :: "r"(dst), "l"(src), "r"(bytes), "r"(mbar) : "memory");
}
__device__ __forceinline__ void ldm_x4(uint32_t* r, uint32_t addr) {
    asm volatile("ldmatrix.sync.aligned.m8n8.x4.shared.b16 {%0,%1,%2,%3}, [%4];"
        : "=r"(r[0]), "=r"(r[1]), "=r"(r[2]), "=r"(r[3]) : "r"(addr));
}
__device__ __forceinline__ void mma16816(float* d, const uint32_t* a, uint32_t b0, uint32_t b1) {
    asm("mma.sync.aligned.m16n8k16.row.col.f32.f16.f16.f32 "
        "{%0,%1,%2,%3}, {%4,%5,%6,%7}, {%8,%9}, {%0,%1,%2,%3};"
        : "+f"(d[0]), "+f"(d[1]), "+f"(d[2]), "+f"(d[3])
        : "r"(a[0]), "r"(a[1]), "r"(a[2]), "r"(a[3]), "r"(b0), "r"(b1));
}
__device__ __forceinline__ float elu1(float x) { return x > 0.f ? x : expm1f(x); }

// ---------------- smem layout ----------------
static constexpr int A_STRIDE = 32768;   // per A stage (Ah 16KB + Al 16KB), 2 stages
static constexpr int W_OFF    = 65536;   // W ring: 4 slots x (Wh 8KB + Wl 8KB)
static constexpr int W_STRIDE = 16384;
static constexpr int GS_OFF   = 131072;  // gates [128][8] f32 = 4KB
static constexpr int BS_OFF   = 135168;  // bias  [EXP][64] f32 <= 2KB
static constexpr int BAR_OFF  = 137216;
static constexpr int SMEM_BYTES = 137472;

// ---------------- blended expert GEMM (mma.sync HMMA, 3-term fp16 split) ----------------
// C[128,64] = act( sum_e g[b,e] * ( A(128xK) @ W_e(64xK)^T + bias_e ) )
template<int EXP, bool GATE, bool ACT, bool OUTF32>
__global__ void __launch_bounds__(256, 1) moe_gemm(
    const __half* __restrict__ Ah, const __half* __restrict__ Al, int kblks,
    const __half* __restrict__ Wh, const __half* __restrict__ Wl, int wnb,
    const float* __restrict__ bias, const float* __restrict__ gate, int ntot,
    __half* __restrict__ Oh, __half* __restrict__ Ol, int okb,
    float* __restrict__ C, int ldc)
{
    extern __shared__ __align__(1024) uint8_t smem[];
    const uint32_t sb = smem_u32(smem);
    const int tid = threadIdx.x;
    const int lane = tid & 31, wid = tid >> 5;
    const int wm = wid & 3, wn = wid >> 2;        // warp grid 4(m) x 2(n)
    const int mblk = blockIdx.y, nblk = blockIdx.x;

    const uint32_t bAf = sb + BAR_OFF;            // 2 x 8B
    const uint32_t bAe = sb + BAR_OFF + 16;       // 2 x 8B
    const uint32_t bWf = sb + BAR_OFF + 32;       // 4 x 8B
    const uint32_t bWe = sb + BAR_OFF + 64;       // 4 x 8B

    if (tid == 0) {
        for (int s = 0; s < 2; s++) { mbar_init(bAf + s*8, 1); mbar_init(bAe + s*8, 256); }
        for (int s = 0; s < 4; s++) { mbar_init(bWf + s*8, 1); mbar_init(bWe + s*8, 256); }
    }
    __syncthreads();

    // stage gates + bias tile
    float* gS = (float*)(smem + GS_OFF);
    float* bS = (float*)(smem + BS_OFF);
    if (GATE) {
        for (int i = tid; i < 128 * EE; i += 256) gS[i] = gate[(size_t)mblk * 128 * EE + i];
    }
    for (int i = tid; i < EXP * 64; i += 256) {
        int e = i >> 6, j = i & 63, o = nblk * 64 + j;
        bS[i] = (o < ntot) ? bias[e * ntot + o] : 0.f;
    }

    const int total = kblks * EXP;
    if (tid == 0) {
        int npro = total < 4 ? total : 4;
        for (int u = 0; u < npro; u++) {
            int kb = u / EXP, e = u % EXP, s = u & 3;
            mbar_expect(bWf + s*8, 16384);
            size_t off = (((size_t)e * wnb + nblk) * kblks + kb) * 4096;
            bulk_g2s(sb + W_OFF + s*W_STRIDE,        Wh + off, 8192, bWf + s*8);
            bulk_g2s(sb + W_OFF + s*W_STRIDE + 8192, Wl + off, 8192, bWf + s*8);
        }
        int na = kblks < 2 ? kblks : 2;
        for (int kb = 0; kb < na; kb++) {
            mbar_expect(bAf + kb*8, 32768);
            size_t off = ((size_t)mblk * kblks + kb) * 8192;
            bulk_g2s(sb + kb*A_STRIDE,         Ah + off, 16384, bAf + kb*8);
            bulk_g2s(sb + kb*A_STRIDE + 16384, Al + off, 16384, bAf + kb*8);
        }
    }
    __syncthreads();

    // precompute swizzled ldmatrix offsets (lanes 0-15: rows, lanes 16-31: +8 halves in k)
    uint32_t offA[2][4], offB[2][4];
#pragma unroll
    for (int i = 0; i < 2; i++)
#pragma unroll
        for (int j = 0; j < 4; j++)
            offA[i][j] = SWZ((uint32_t)((wm*32 + i*16 + (lane & 15)) * 128 + j*32 + (lane >> 4) * 16));
#pragma unroll
    for (int p = 0; p < 2; p++)
#pragma unroll
        for (int j = 0; j < 4; j++)
            offB[p][j] = SWZ((uint32_t)((wn*32 + p*16 + (lane & 15)) * 128 + j*32 + (lane >> 4) * 16));

    float acc[2][4][4];
#pragma unroll
    for (int i = 0; i < 2; i++)
#pragma unroll
        for (int n8 = 0; n8 < 4; n8++)
#pragma unroll
            for (int q = 0; q < 4; q++) acc[i][n8][q] = 0.f;

    int wu = 0;
#pragma unroll 1
    for (int kb = 0; kb < kblks; kb++) {
        int as = kb & 1;
        mbar_wait(bAf + as*8, (kb >> 1) & 1);
        const uint32_t Ab = sb + as*A_STRIDE;
        uint32_t aH[2][4][4], aL[2][4][4];   // A fragments resident across expert loop
#pragma unroll
        for (int i = 0; i < 2; i++)
#pragma unroll
            for (int j = 0; j < 4; j++) {
                ldm_x4(aH[i][j], Ab + offA[i][j]);
                ldm_x4(aL[i][j], Ab + 16384 + offA[i][j]);
            }
#pragma unroll 1
        for (int e = 0; e < EXP; e++) {
            int s = wu & 3;
            mbar_wait(bWf + s*8, (wu >> 2) & 1);
            const uint32_t Wb = sb + W_OFF + s*W_STRIDE;
            if (GATE) {
                float part[2][4][4];
#pragma unroll
                for (int i = 0; i < 2; i++)
#pragma unroll
                    for (int n8 = 0; n8 < 4; n8++)
#pragma unroll
                        for (int q = 0; q < 4; q++) part[i][n8][q] = 0.f;
#pragma unroll
                for (int j = 0; j < 4; j++) {
                    uint32_t b0h[4], b1h[4], b0l[4], b1l[4];
                    ldm_x4(b0h, Wb + offB[0][j]);
                    ldm_x4(b1h, Wb + offB[1][j]);
                    ldm_x4(b0l, Wb + 8192 + offB[0][j]);
                    ldm_x4(b1l, Wb + 8192 + offB[1][j]);
#pragma unroll
                    for (int i = 0; i < 2; i++)
#pragma unroll
                        for (int n8 = 0; n8 < 4; n8++) {
                            const uint32_t* bh = (n8 < 2) ? b0h : b1h;
                            const uint32_t* bl = (n8 < 2) ? b0l : b1l;
                            int q = n8 & 1;
                            mma16816(part[i][n8], aH[i][j], bh[q], bh[2 + q]);
                            mma16816(part[i][n8], aL[i][j], bh[q], bh[2 + q]);
                            mma16816(part[i][n8], aH[i][j], bl[q], bl[2 + q]);
                        }
                }
                int r0 = wm*32 + (lane >> 2);
                float g0 = gS[(r0 + 0)  * EE + e], g1 = gS[(r0 + 8)  * EE + e];
                float g2 = gS[(r0 + 16) * EE + e], g3 = gS[(r0 + 24) * EE + e];
#pragma unroll
                for (int n8 = 0; n8 < 4; n8++) {
                    acc[0][n8][0] += g0 * part[0][n8][0];
                    acc[0][n8][1] += g0 * part[0][n8][1];
                    acc[0][n8][2] += g1 * part[0][n8][2];
                    acc[0][n8][3] += g1 * part[0][n8][3];
                    acc[1][n8][0] += g2 * part[1][n8][0];
                    acc[1][n8][1] += g2 * part[1][n8][1];
                    acc[1][n8][2] += g3 * part[1][n8][2];
                    acc[1][n8][3] += g3 * part[1][n8][3];
                }
            } else {
#pragma unroll
                for (int j = 0; j < 4; j++) {
                    uint32_t b0h[4], b1h[4], b0l[4], b1l[4];
                    ldm_x4(b0h, Wb + offB[0][j]);
                    ldm_x4(b1h, Wb + offB[1][j]);
                    ldm_x4(b0l, Wb + 8192 + offB[0][j]);
                    ldm_x4(b1l, Wb + 8192 + offB[1][j]);
#pragma unroll
                    for (int i = 0; i < 2; i++)
#pragma unroll
                        for (int n8 = 0; n8 < 4; n8++) {
                            const uint32_t* bh = (n8 < 2) ? b0h : b1h;
                            const uint32_t* bl = (n8 < 2) ? b0l : b1l;
                            int q = n8 & 1;
                            mma16816(acc[i][n8], aH[i][j], bh[q], bh[2 + q]);
                            mma16816(acc[i][n8], aL[i][j], bh[q], bh[2 + q]);
                            mma16816(acc[i][n8], aH[i][j], bl[q], bl[2 + q]);
                        }
                }
            }
            mbar_arrive(bWe + s*8);
            if (tid == 0 && wu + 4 < total) {
                mbar_wait(bWe + s*8, (wu >> 2) & 1);
                int u2 = wu + 4, kb2 = u2 / EXP, e2 = u2 % EXP;
                mbar_expect(bWf + s*8, 16384);
                size_t off = (((size_t)e2 * wnb + nblk) * kblks + kb2) * 4096;
                bulk_g2s(sb + W_OFF + s*W_STRIDE,        Wh + off, 8192, bWf + s*8);
                bulk_g2s(sb + W_OFF + s*W_STRIDE + 8192, Wl + off, 8192, bWf + s*8);
            }
            wu++;
        }
        mbar_arrive(bAe + as*8);
        if (tid == 0 && kb + 2 < kblks) {
            mbar_wait(bAe + as*8, (kb >> 1) & 1);
            mbar_expect(bAf + as*8, 32768);
            size_t off = ((size_t)mblk * kblks + kb + 2) * 8192;
            bulk_g2s(sb + as*A_STRIDE,         Ah + off, 16384, bAf + as*8);
            bulk_g2s(sb + as*A_STRIDE + 16384, Al + off, 16384, bAf + as*8);
        }
    }

    // ---- epilogue: blended bias + activation + store ----
    const int rbase = wm*32 + (lane >> 2);
    const int cbase = wn*32 + (lane & 3) * 2;
#pragma unroll
    for (int i = 0; i < 2; i++) {
#pragma unroll
        for (int hf = 0; hf < 2; hf++) {
            int lr = rbase + i*16 + hf*8;
            int grow = mblk*128 + lr;
#pragma unroll
            for (int n8 = 0; n8 < 4; n8++) {
                int cl = cbase + n8*8;
                float v0 = acc[i][n8][hf*2 + 0];
                float v1 = acc[i][n8][hf*2 + 1];
                if (GATE) {
                    float s0 = 0.f, s1 = 0.f;
#pragma unroll
                    for (int e = 0; e < EXP; e++) {
                        float g = gS[lr * EE + e];
                        s0 += g * bS[e*64 + cl];
                        s1 += g * bS[e*64 + cl + 1];
                    }
                    v0 += s0; v1 += s1;
                } else { v0 += bS[cl]; v1 += bS[cl + 1]; }
                if (ACT) { v0 = elu1(v0); v1 = elu1(v1); }
                if (OUTF32) {
                    int c = nblk*64 + cl;
                    if (c < ntot)     C[(size_t)grow * ldc + c]     = v0;
                    if (c + 1 < ntot) C[(size_t)grow * ldc + c + 1] = v1;
                } else {
                    __half h0 = __float2half_rn(v0), h1 = __float2half_rn(v1);
                    __half l0 = __float2half_rn(v0 - __half2float(h0));
                    __half l1 = __float2half_rn(v1 - __half2float(h1));
                    uint32_t off = SWZ((uint32_t)(lr * 128 + cl * 2));
                    uint8_t* bh  = (uint8_t*)(Oh + ((size_t)mblk * okb + nblk) * 8192);
                    uint8_t* blo = (uint8_t*)(Ol + ((size_t)mblk * okb + nblk) * 8192);
                    *(__half2*)(bh + off)  = __halves2half2(h0, h1);
                    *(__half2*)(blo + off) = __halves2half2(l0, l1);
                }
            }
        }
    }
}

// ---------------- prepack: fp32 -> fp16 hi/lo split, SW128-swizzled blobs ----------------
__device__ __forceinline__ void split_store(uint8_t* bh, uint8_t* bl, uint32_t sw, float4 v) {
    float vv[4] = {v.x, v.y, v.z, v.w};
    uint32_t h[4], l[4];
#pragma unroll
    for (int q = 0; q < 4; q++) {
        __half hh = __float2half_rn(vv[q]);
        __half ll = __float2half_rn(vv[q] - __half2float(hh));
        h[q] = (uint32_t)__half_as_ushort(hh);
        l[q] = (uint32_t)__half_as_ushort(ll);
    }
    *(uint2*)(bh + sw) = make_uint2(h[0] | (h[1] << 16), h[2] | (h[3] << 16));
    *(uint2*)(bl + sw) = make_uint2(l[0] | (l[1] << 16), l[2] | (l[3] << 16));
}

__global__ void prepack_w(const float* __restrict__ W, __half* __restrict__ Dh, __half* __restrict__ Dl,
                          int N, int K, int nblks, int kblks) {
    int t = blockIdx.x;
    int kb = t % kblks, nb = (t / kblks) % nblks, e = t / (kblks * nblks);
    const float* src = W + (size_t)e * N * K;
    uint8_t* bh = (uint8_t*)(Dh + (size_t)t * 4096);
    uint8_t* bl = (uint8_t*)(Dl + (size_t)t * 4096);
    for (int i = threadIdx.x; i < 1024; i += 256) {
        int r = i >> 4, c4 = i & 15;
        int n = nb * 64 + r, k = kb * 64 + c4 * 4;
        float4 v = make_float4(0.f, 0.f, 0.f, 0.f);
        if (n < N && k < K) v = *(const float4*)(src + (size_t)n * K + k);
        split_store(bh, bl, SWZ((uint32_t)(r * 128 + c4 * 8)), v);
    }
}

__global__ void prepack_a0(const float* __restrict__ x, const float* __restrict__ z) {
    int t = blockIdx.x;              // mblk*5 + kb
    int kb = t % 5, mb = t / 5;
    uint8_t* bh = (uint8_t*)(g_A0h + (size_t)t * 8192);
    uint8_t* bl = (uint8_t*)(g_A0l + (size_t)t * 8192);
    for (int i = threadIdx.x; i < 2048; i += 256) {
        int r = i >> 4, c4 = i & 15;
        int row = mb * 128 + r, k = kb * 64 + c4 * 4;
        float4 v;
        if (k < D3) v = *(const float4*)(x + (size_t)row * D3 + k);
        else        v = *(const float4*)(z + (size_t)row * LZ + (k - D3));
        split_store(bh, bl, SWZ((uint32_t)(r * 128 + c4 * 8)), v);
    }
}

__global__ void prepack_ztails(const float* __restrict__ z) {
    int mb = blockIdx.x;
    size_t off = ((size_t)mb * 9 + 8) * 8192;
    for (int i = threadIdx.x; i < 2048; i += 256) {
        int r = i >> 4, c4 = i & 15;
        int row = mb * 128 + r, k = c4 * 4;
        float4 v = make_float4(0.f, 0.f, 0.f, 0.f);
        if (k < LZ) v = *(const float4*)(z + (size_t)row * LZ + k);
        uint32_t sw = SWZ((uint32_t)(r * 128 + c4 * 8));
        split_store((uint8_t*)(g_A1h + off), (uint8_t*)(g_A1l + off), sw, v);
        split_store((uint8_t*)(g_A2h + off), (uint8_t*)(g_A2l + off), sw, v);
    }
}

// ---------------- gating logits + softmax over E=8 ----------------
__global__ void logits_softmax(const float* __restrict__ h2,
                               const float* __restrict__ gW3,
                               const float* __restrict__ gb3) {
    int tid = blockIdx.x * blockDim.x + threadIdx.x;
    int row = tid >> 3, e = tid & 7;
    if (row >= BB) return;
    float s = gb3[e];
    const float* hr = h2 + (size_t)row * GHD;
    const float* wr = gW3 + (size_t)e * GHD;
#pragma unroll 8
    for (int i = 0; i < GHD; i++) s += hr[i] * wr[i];
    float m = s;
#pragma unroll
    for (int o = 4; o; o >>= 1) m = fmaxf(m, __shfl_xor_sync(0xffffffffu, m, o));
    float ex = expf(s - m);
    float sum = ex;
#pragma unroll
    for (int o = 4; o; o >>= 1) sum += __shfl_xor_sync(0xffffffffu, sum, o);
    g_gate[tid] = ex / sum;
}

// ---------------- host ----------------
extern "C" void kernel_launch(void* const* d_in, const int* in_sizes, int n_in,
                              void* d_out, int out_size) {
    const float* x   = (const float*)d_in[0];
    const float* z   = (const float*)d_in[1];
    const float* W0  = (const float*)d_in[2];
    const float* b0  = (const float*)d_in[3];
    const float* W1  = (const float*)d_in[4];
    const float* b1  = (const float*)d_in[5];
    const float* W2  = (const float*)d_in[6];
    const float* b2  = (const float*)d_in[7];
    const float* W3  = (const float*)d_in[8];
    const float* b3  = (const float*)d_in[9];
    const float* gW1 = (const float*)d_in[10];
    const float* gb1 = (const float*)d_in[11];
    const float* gW2 = (const float*)d_in[12];
    const float* gb2 = (const float*)d_in[13];
    const float* gW3 = (const float*)d_in[14];
    const float* gb3 = (const float*)d_in[15];
    float* out = (float*)d_out;
    (void)in_sizes; (void)n_in; (void)out_size;

    __half *A0h,*A0l,*A1h,*A1l,*A2h,*A2l,*A3h,*A3l,*G1h,*G1l;
    __half *pW0h,*pW0l,*pW1h,*pW1l,*pW2h,*pW2l,*pW3h,*pW3l,*pg1h,*pg1l,*pg2h,*pg2l;
    float *gh2, *gate;
    cudaGetSymbolAddress((void**)&A0h, g_A0h); cudaGetSymbolAddress((void**)&A0l, g_A0l);
    cudaGetSymbolAddress((void**)&A1h, g_A1h); cudaGetSymbolAddress((void**)&A1l, g_A1l);
    cudaGetSymbolAddress((void**)&A2h, g_A2h); cudaGetSymbolAddress((void**)&A2l, g_A2l);
    cudaGetSymbolAddress((void**)&A3h, g_A3h); cudaGetSymbolAddress((void**)&A3l, g_A3l);
    cudaGetSymbolAddress((void**)&G1h, g_G1h); cudaGetSymbolAddress((void**)&G1l, g_G1l);
    cudaGetSymbolAddress((void**)&pW0h, g_W0h); cudaGetSymbolAddress((void**)&pW0l, g_W0l);
    cudaGetSymbolAddress((void**)&pW1h, g_W1h); cudaGetSymbolAddress((void**)&pW1l, g_W1l);
    cudaGetSymbolAddress((void**)&pW2h, g_W2h); cudaGetSymbolAddress((void**)&pW2l, g_W2l);
    cudaGetSymbolAddress((void**)&pW3h, g_W3h); cudaGetSymbolAddress((void**)&pW3l, g_W3l);
    cudaGetSymbolAddress((void**)&pg1h, g_gW1h); cudaGetSymbolAddress((void**)&pg1l, g_gW1l);
    cudaGetSymbolAddress((void**)&pg2h, g_gW2h); cudaGetSymbolAddress((void**)&pg2l, g_gW2l);
    cudaGetSymbolAddress((void**)&gh2, g_gh2); cudaGetSymbolAddress((void**)&gate, g_gate);

    cudaFuncSetAttribute(moe_gemm<1,false,true,false>, cudaFuncAttributeMaxDynamicSharedMemorySize, SMEM_BYTES);
    cudaFuncSetAttribute(moe_gemm<1,false,true,true>,  cudaFuncAttributeMaxDynamicSharedMemorySize, SMEM_BYTES);
    cudaFuncSetAttribute(moe_gemm<8,true,true,false>,  cudaFuncAttributeMaxDynamicSharedMemorySize, SMEM_BYTES);
    cudaFuncSetAttribute(moe_gemm<8,true,false,true>,  cudaFuncAttributeMaxDynamicSharedMemorySize, SMEM_BYTES);

    // prepack weights + inputs
    prepack_w<<<8*8*5, 256>>>(W0, pW0h, pW0l, HH, 320, 8, 5);
    prepack_w<<<8*8*9, 256>>>(W1, pW1h, pW1l, HH, 544, 8, 9);
    prepack_w<<<8*8*9, 256>>>(W2, pW2h, pW2l, HH, 544, 8, 9);
    prepack_w<<<8*2*8, 256>>>(W3, pW3h, pW3l, OO, 512, 2, 8);
    prepack_w<<<1*2*5, 256>>>(gW1, pg1h, pg1l, GHD, 320, 2, 5);
    prepack_w<<<1*2*2, 256>>>(gW2, pg2h, pg2l, GHD, GHD, 2, 2);
    prepack_a0<<<MBK*5, 256>>>(x, z);
    prepack_ztails<<<MBK, 256>>>(z);

    // gating MLP on tensor cores
    moe_gemm<1,false,true,false><<<dim3(2, MBK), 256, SMEM_BYTES>>>(
        A0h, A0l, 5, pg1h, pg1l, 2, gb1, nullptr, GHD, G1h, G1l, 2, nullptr, 0);
    moe_gemm<1,false,true,true><<<dim3(2, MBK), 256, SMEM_BYTES>>>(
        G1h, G1l, 2, pg2h, pg2l, 2, gb2, nullptr, GHD, nullptr, nullptr, 0, gh2, GHD);
    logits_softmax<<<BB*EE/256, 256>>>(gh2, gW3, gb3);

    // blended expert layers
    moe_gemm<8,true,true,false><<<dim3(8, MBK), 256, SMEM_BYTES>>>(
        A0h, A0l, 5, pW0h, pW0l, 8, b0, gate, HH, A1h, A1l, 9, nullptr, 0);
    moe_gemm<8,true,true,false><<<dim3(8, MBK), 256, SMEM_BYTES>>>(
        A1h, A1l, 9, pW1h, pW1l, 8, b1, gate, HH, A2h, A2l, 9, nullptr, 0);
    moe_gemm<8,true,true,false><<<dim3(8, MBK), 256, SMEM_BYTES>>>(
        A2h, A2l, 9, pW2h, pW2l, 8, b2, gate, HH, A3h, A3l, 8, nullptr, 0);
    moe_gemm<8,true,false,true><<<dim3(2, MBK), 256, SMEM_BYTES>>>(
        A3h, A3l, 8, pW3h, pW3l, 2, b3, gate, OO, nullptr, nullptr, 0, out, OO);
}

// round 6
// speedup vs baseline: 9.0474x; 1.0849x over previous
#include <cuda_runtime.h>
#include <cuda_fp16.h>
#include <math.h>
#include <stdint.h>

// ---------------- problem constants ----------------
static constexpr int BB=4096, D3=288, LZ=32, HH=512, OO=96, EE=8, GHD=128;
static constexpr int MBK = BB/128;   // 32 m-blocks

#define SWZ(o) ((o) ^ (((o) >> 3) & 0x70))

// ---------------- global scratch (pre-swizzled SW128 blobs; no allocs allowed) ----------------
// A blobs: [mblk][kblk] tiles of 128 rows x 64 half cols = 8192 halves = 16KB
// W blobs: [e][nblk][kblk] tiles of 64 rows x 64 half cols = 4096 halves = 8KB
__device__ __align__(128) __half g_A0h[MBK*5*8192], g_A0l[MBK*5*8192];
__device__ __align__(128) __half g_A1h[MBK*9*8192], g_A1l[MBK*9*8192];
__device__ __align__(128) __half g_A2h[MBK*9*8192], g_A2l[MBK*9*8192];
__device__ __align__(128) __half g_A3h[MBK*8*8192], g_A3l[MBK*8*8192];
__device__ __align__(128) __half g_G1h[MBK*2*8192], g_G1l[MBK*2*8192];
__device__ __align__(128) __half g_W0h[8*8*5*4096], g_W0l[8*8*5*4096];
__device__ __align__(128) __half g_W1h[8*8*9*4096], g_W1l[8*8*9*4096];
__device__ __align__(128) __half g_W2h[8*8*9*4096], g_W2l[8*8*9*4096];
__device__ __align__(128) __half g_W3h[8*2*8*4096], g_W3l[8*2*8*4096];
__device__ __align__(128) __half g_gW1h[2*5*4096],  g_gW1l[2*5*4096];
__device__ __align__(128) __half g_gW2h[2*2*4096],  g_gW2l[2*2*4096];
__device__ float g_gh2[BB*GHD];
__device__ float g_gate[BB*EE];

// ---------------- PTX helpers ----------------
__device__ __forceinline__ uint32_t smem_u32(const void* p) {
    uint32_t a;
    asm("{ .reg .u64 t; cvta.to.shared.u64 t, %1; cvt.u32.u64 %0, t; }" : "=r"(a) : "l"(p));
    return a;
}
__device__ __forceinline__ void mbar_init(uint32_t m, uint32_t c) {
    asm volatile("mbarrier.init.shared.b64 [%0], %1;" :: "r"(m), "r"(c) : "memory");
}
__device__ __forceinline__ void mbar_expect(uint32_t m, uint32_t b) {
    asm volatile("mbarrier.arrive.expect_tx.shared.b64 _, [%0], %1;" :: "r"(m), "r"(b) : "memory");
}
__device__ __forceinline__ void mbar_arrive(uint32_t m) {
    asm volatile("mbarrier.arrive.shared.b64 _, [%0];" :: "r"(m) : "memory");
}
__device__ __forceinline__ void mbar_wait(uint32_t m, uint32_t ph) {
    uint32_t done;
    asm volatile("{\n\t.reg .pred p;\n\t"
        "mbarrier.try_wait.parity.acquire.cta.shared::cta.b64 p, [%1], %2;\n\t"
        "selp.b32 %0, 1, 0, p;\n\t}" : "=r"(done) : "r"(m), "r"(ph) : "memory");
    while (!done) {
        asm volatile("{\n\t.reg .pred p;\n\t"
            "mbarrier.try_wait.parity.acquire.cta.shared::cta.b64 p, [%1], %2, 0x989680;\n\t"
            "selp.b32 %0, 1, 0, p;\n\t}" : "=r"(done) : "r"(m), "r"(ph) : "memory");
    }
}
__device__ __forceinline__ void bulk_g2s(uint32_t dst, const void* src, uint32_t bytes, uint32_t mbar) {
    asm volatile("cp.async.bulk.shared::cluster.global.mbarrier::complete_tx::bytes [%0], [%1], %2, [%3];"
        :: "r"(dst), "l"(src), "r"(bytes), "r"(mbar) : "memory");
}
__device__ __forceinline__ void ldm_x4(uint32_t* r, uint32_t addr) {
    asm volatile("ldmatrix.sync.aligned.m8n8.x4.shared.b16 {%0,%1,%2,%3}, [%4];"
        : "=r"(r[0]), "=r"(r[1]), "=r"(r[2]), "=r"(r[3]) : "r"(addr));
}
__device__ __forceinline__ void mma16816(float* d, const uint32_t* a, uint32_t b0, uint32_t b1) {
    asm("mma.sync.aligned.m16n8k16.row.col.f32.f16.f16.f32 "
        "{%0,%1,%2,%3}, {%4,%5,%6,%7}, {%8,%9}, {%0,%1,%2,%3};"
        : "+f"(d[0]), "+f"(d[1]), "+f"(d[2]), "+f"(d[3])
        : "r"(a[0]), "r"(a[1]), "r"(a[2]), "r"(a[3]), "r"(b0), "r"(b1));
}
__device__ __forceinline__ float elu1(float x) { return x > 0.f ? x : expm1f(x); }

// ---------------- smem layout ----------------
static constexpr int A_STRIDE = 32768;   // per A stage (Ah 16KB + Al 16KB), 2 stages
static constexpr int W_OFF    = 65536;   // W ring: 8 slots x (Wh 8KB + Wl 8KB) = 128KB
static constexpr int W_STRIDE = 16384;
static constexpr int GS_OFF   = 196608;  // gates [128][8] f32 = 4KB
static constexpr int BS_OFF   = 200704;  // bias  [EXP][64] f32 <= 2KB
static constexpr int BAR_OFF  = 202752;
static constexpr int SMEM_BYTES = 203008;

static constexpr int NTHREADS = 288;     // 8 compute warps + 1 producer warp

// ---------------- blended expert GEMM (mma.sync HMMA, 3-term fp16 split) ----------------
// C[128,64] = act( sum_e g[b,e] * ( A(128xK) @ W_e(64xK)^T + bias_e ) )
template<int EXP, bool GATE, bool ACT, bool OUTF32>
__global__ void __launch_bounds__(NTHREADS, 1) moe_gemm(
    const __half* __restrict__ Ah, const __half* __restrict__ Al, int kblks,
    const __half* __restrict__ Wh, const __half* __restrict__ Wl, int wnb,
    const float* __restrict__ bias, const float* __restrict__ gate, int ntot,
    __half* __restrict__ Oh, __half* __restrict__ Ol, int okb,
    float* __restrict__ C, int ldc)
{
    extern __shared__ __align__(1024) uint8_t smem[];
    const uint32_t sb = smem_u32(smem);
    const int tid = threadIdx.x;
    const int lane = tid & 31, wid = tid >> 5;
    const int wm = wid & 3, wn = (wid >> 2) & 1;   // warp grid 4(m) x 2(n) (compute warps 0-7)
    const int mblk = blockIdx.y, nblk = blockIdx.x;

    const uint32_t bAf = sb + BAR_OFF;             // 2 x 8B, count 1
    const uint32_t bAe = sb + BAR_OFF + 16;        // 2 x 8B, count 8
    const uint32_t bWf = sb + BAR_OFF + 32;        // 8 x 8B, count 1
    const uint32_t bWe = sb + BAR_OFF + 96;        // 8 x 8B, count 8

    if (tid == 0) {
        for (int s = 0; s < 2; s++) { mbar_init(bAf + s*8, 1); mbar_init(bAe + s*8, 8); }
        for (int s = 0; s < 8; s++) { mbar_init(bWf + s*8, 1); mbar_init(bWe + s*8, 8); }
    }

    // stage gates + bias tile
    float* gS = (float*)(smem + GS_OFF);
    float* bS = (float*)(smem + BS_OFF);
    if (GATE) {
        for (int i = tid; i < 128 * EE; i += NTHREADS) gS[i] = gate[(size_t)mblk * 128 * EE + i];
    }
    for (int i = tid; i < EXP * 64; i += NTHREADS) {
        int e = i >> 6, j = i & 63, o = nblk * 64 + j;
        bS[i] = (o < ntot) ? bias[e * ntot + o] : 0.f;
    }
    __syncthreads();

    if (wid == 8) {
        // ---------------- dedicated producer warp (lane 0 only) ----------------
        if (lane == 0) {
            for (int kb = 0; kb < kblks; kb++) {
                int as = kb & 1;
                if (kb >= 2) mbar_wait(bAe + as*8, ((kb >> 1) & 1) ^ 1);
                mbar_expect(bAf + as*8, 32768);
                size_t aoff = ((size_t)mblk * kblks + kb) * 8192;
                bulk_g2s(sb + as*A_STRIDE,         Ah + aoff, 16384, bAf + as*8);
                bulk_g2s(sb + as*A_STRIDE + 16384, Al + aoff, 16384, bAf + as*8);
                for (int e = 0; e < EXP; e++) {
                    int wu = kb * EXP + e, s = wu & 7;
                    if (wu >= 8) mbar_wait(bWe + s*8, ((wu >> 3) & 1) ^ 1);
                    mbar_expect(bWf + s*8, 16384);
                    size_t woff = (((size_t)e * wnb + nblk) * kblks + kb) * 4096;
                    bulk_g2s(sb + W_OFF + s*W_STRIDE,        Wh + woff, 8192, bWf + s*8);
                    bulk_g2s(sb + W_OFF + s*W_STRIDE + 8192, Wl + woff, 8192, bWf + s*8);
                }
            }
        }
        return;  // producer warp done (no epilogue fragments)
    }

    // ---------------- compute warps (0-7) ----------------
    // precompute swizzled ldmatrix offsets
    uint32_t offA[2][4], offB[2][4];
#pragma unroll
    for (int i = 0; i < 2; i++)
#pragma unroll
        for (int j = 0; j < 4; j++)
            offA[i][j] = SWZ((uint32_t)((wm*32 + i*16 + (lane & 15)) * 128 + j*32 + (lane >> 4) * 16));
#pragma unroll
    for (int p = 0; p < 2; p++)
#pragma unroll
        for (int j = 0; j < 4; j++)
            offB[p][j] = SWZ((uint32_t)((wn*32 + p*16 + (lane & 15)) * 128 + j*32 + (lane >> 4) * 16));

    float acc[2][4][4];
#pragma unroll
    for (int i = 0; i < 2; i++)
#pragma unroll
        for (int n8 = 0; n8 < 4; n8++)
#pragma unroll
            for (int q = 0; q < 4; q++) acc[i][n8][q] = 0.f;

    int wu = 0;
#pragma unroll 1
    for (int kb = 0; kb < kblks; kb++) {
        int as = kb & 1;
        mbar_wait(bAf + as*8, (kb >> 1) & 1);
        const uint32_t Ab = sb + as*A_STRIDE;
        uint32_t aH[2][4][4], aL[2][4][4];   // A fragments resident across expert loop
#pragma unroll
        for (int i = 0; i < 2; i++)
#pragma unroll
            for (int j = 0; j < 4; j++) {
                ldm_x4(aH[i][j], Ab + offA[i][j]);
                ldm_x4(aL[i][j], Ab + 16384 + offA[i][j]);
            }
        if (lane == 0) mbar_arrive(bAe + as*8);   // frags in regs -> stage free
#pragma unroll 1
        for (int e = 0; e < EXP; e++) {
            int s = wu & 7;
            mbar_wait(bWf + s*8, (wu >> 3) & 1);
            const uint32_t Wb = sb + W_OFF + s*W_STRIDE;
            if (GATE) {
                float part[2][4][4];
#pragma unroll
                for (int i = 0; i < 2; i++)
#pragma unroll
                    for (int n8 = 0; n8 < 4; n8++)
#pragma unroll
                        for (int q = 0; q < 4; q++) part[i][n8][q] = 0.f;
#pragma unroll
                for (int j = 0; j < 4; j++) {
                    uint32_t b0h[4], b1h[4], b0l[4], b1l[4];
                    ldm_x4(b0h, Wb + offB[0][j]);
                    ldm_x4(b1h, Wb + offB[1][j]);
                    ldm_x4(b0l, Wb + 8192 + offB[0][j]);
                    ldm_x4(b1l, Wb + 8192 + offB[1][j]);
#pragma unroll
                    for (int i = 0; i < 2; i++)
#pragma unroll
                        for (int n8 = 0; n8 < 4; n8++) {
                            const uint32_t* bh = (n8 < 2) ? b0h : b1h;
                            const uint32_t* bl = (n8 < 2) ? b0l : b1l;
                            int q = n8 & 1;
                            mma16816(part[i][n8], aH[i][j], bh[q], bh[2 + q]);
                            mma16816(part[i][n8], aL[i][j], bh[q], bh[2 + q]);
                            mma16816(part[i][n8], aH[i][j], bl[q], bl[2 + q]);
                        }
                }
                if (lane == 0) mbar_arrive(bWe + s*8);
                int r0 = wm*32 + (lane >> 2);
                float g0 = gS[(r0 + 0)  * EE + e], g1 = gS[(r0 + 8)  * EE + e];
                float g2 = gS[(r0 + 16) * EE + e], g3 = gS[(r0 + 24) * EE + e];
#pragma unroll
                for (int n8 = 0; n8 < 4; n8++) {
                    acc[0][n8][0] += g0 * part[0][n8][0];
                    acc[0][n8][1] += g0 * part[0][n8][1];
                    acc[0][n8][2] += g1 * part[0][n8][2];
                    acc[0][n8][3] += g1 * part[0][n8][3];
                    acc[1][n8][0] += g2 * part[1][n8][0];
                    acc[1][n8][1] += g2 * part[1][n8][1];
                    acc[1][n8][2] += g3 * part[1][n8][2];
                    acc[1][n8][3] += g3 * part[1][n8][3];
                }
            } else {
#pragma unroll
                for (int j = 0; j < 4; j++) {
                    uint32_t b0h[4], b1h[4], b0l[4], b1l[4];
                    ldm_x4(b0h, Wb + offB[0][j]);
                    ldm_x4(b1h, Wb + offB[1][j]);
                    ldm_x4(b0l, Wb + 8192 + offB[0][j]);
                    ldm_x4(b1l, Wb + 8192 + offB[1][j]);
#pragma unroll
                    for (int i = 0; i < 2; i++)
#pragma unroll
                        for (int n8 = 0; n8 < 4; n8++) {
                            const uint32_t* bh = (n8 < 2) ? b0h : b1h;
                            const uint32_t* bl = (n8 < 2) ? b0l : b1l;
                            int q = n8 & 1;
                            mma16816(acc[i][n8], aH[i][j], bh[q], bh[2 + q]);
                            mma16816(acc[i][n8], aL[i][j], bh[q], bh[2 + q]);
                            mma16816(acc[i][n8], aH[i][j], bl[q], bl[2 + q]);
                        }
                }
                if (lane == 0) mbar_arrive(bWe + s*8);
            }
            wu++;
        }
    }

    // ---- epilogue: blended bias + activation + store ----
    const int rbase = wm*32 + (lane >> 2);
    const int cbase = wn*32 + (lane & 3) * 2;
#pragma unroll
    for (int i = 0; i < 2; i++) {
#pragma unroll
        for (int hf = 0; hf < 2; hf++) {
            int lr = rbase + i*16 + hf*8;
            int grow = mblk*128 + lr;
#pragma unroll
            for (int n8 = 0; n8 < 4; n8++) {
                int cl = cbase + n8*8;
                float v0 = acc[i][n8][hf*2 + 0];
                float v1 = acc[i][n8][hf*2 + 1];
                if (GATE) {
                    float s0 = 0.f, s1 = 0.f;
#pragma unroll
                    for (int e = 0; e < EXP; e++) {
                        float g = gS[lr * EE + e];
                        s0 += g * bS[e*64 + cl];
                        s1 += g * bS[e*64 + cl + 1];
                    }
                    v0 += s0; v1 += s1;
                } else { v0 += bS[cl]; v1 += bS[cl + 1]; }
                if (ACT) { v0 = elu1(v0); v1 = elu1(v1); }
                if (OUTF32) {
                    int c = nblk*64 + cl;
                    if (c < ntot)     C[(size_t)grow * ldc + c]     = v0;
                    if (c + 1 < ntot) C[(size_t)grow * ldc + c + 1] = v1;
                } else {
                    __half h0 = __float2half_rn(v0), h1 = __float2half_rn(v1);
                    __half l0 = __float2half_rn(v0 - __half2float(h0));
                    __half l1 = __float2half_rn(v1 - __half2float(h1));
                    uint32_t off = SWZ((uint32_t)(lr * 128 + cl * 2));
                    uint8_t* bh  = (uint8_t*)(Oh + ((size_t)mblk * okb + nblk) * 8192);
                    uint8_t* blo = (uint8_t*)(Ol + ((size_t)mblk * okb + nblk) * 8192);
                    *(__half2*)(bh + off)  = __halves2half2(h0, h1);
                    *(__half2*)(blo + off) = __halves2half2(l0, l1);
                }
            }
        }
    }
}

// ---------------- prepack: fp32 -> fp16 hi/lo split, SW128-swizzled blobs ----------------
__device__ __forceinline__ void split_store(uint8_t* bh, uint8_t* bl, uint32_t sw, float4 v) {
    float vv[4] = {v.x, v.y, v.z, v.w};
    uint32_t h[4], l[4];
#pragma unroll
    for (int q = 0; q < 4; q++) {
        __half hh = __float2half_rn(vv[q]);
        __half ll = __float2half_rn(vv[q] - __half2float(hh));
        h[q] = (uint32_t)__half_as_ushort(hh);
        l[q] = (uint32_t)__half_as_ushort(ll);
    }
    *(uint2*)(bh + sw) = make_uint2(h[0] | (h[1] << 16), h[2] | (h[3] << 16));
    *(uint2*)(bl + sw) = make_uint2(l[0] | (l[1] << 16), l[2] | (l[3] << 16));
}

struct PWJob { const float* W; __half* Dh; __half* Dl; int N, K, nblks, kblks, blk0, cnt; };
struct PWJobs { PWJob j[6]; };

__global__ void prepack_w_all(PWJobs jobs) {
    int b = blockIdx.x;
#pragma unroll 1
    for (int ji = 0; ji < 6; ji++) {
        const PWJob& J = jobs.j[ji];
        if (b < J.blk0 || b >= J.blk0 + J.cnt) continue;
        int t = b - J.blk0;
        int kb = t % J.kblks, nb = (t / J.kblks) % J.nblks, e = t / (J.kblks * J.nblks);
        const float* src = J.W + (size_t)e * J.N * J.K;
        uint8_t* bh = (uint8_t*)(J.Dh + (size_t)t * 4096);
        uint8_t* bl = (uint8_t*)(J.Dl + (size_t)t * 4096);
        for (int i = threadIdx.x; i < 1024; i += 256) {
            int r = i >> 4, c4 = i & 15;
            int n = nb * 64 + r, k = kb * 64 + c4 * 4;
            float4 v = make_float4(0.f, 0.f, 0.f, 0.f);
            if (n < J.N && k < J.K) v = *(const float4*)(src + (size_t)n * J.K + k);
            split_store(bh, bl, SWZ((uint32_t)(r * 128 + c4 * 8)), v);
        }
        return;
    }
}

__global__ void prepack_a_all(const float* __restrict__ x, const float* __restrict__ z) {
    int b = blockIdx.x;
    if (b < MBK * 5) {
        int kb = b % 5, mb = b / 5;
        uint8_t* bh = (uint8_t*)(g_A0h + (size_t)b * 8192);
        uint8_t* bl = (uint8_t*)(g_A0l + (size_t)b * 8192);
        for (int i = threadIdx.x; i < 2048; i += 256) {
            int r = i >> 4, c4 = i & 15;
            int row = mb * 128 + r, k = kb * 64 + c4 * 4;
            float4 v;
            if (k < D3) v = *(const float4*)(x + (size_t)row * D3 + k);
            else        v = *(const float4*)(z + (size_t)row * LZ + (k - D3));
            split_store(bh, bl, SWZ((uint32_t)(r * 128 + c4 * 8)), v);
        }
    } else {
        int mb = b - MBK * 5;
        size_t off = ((size_t)mb * 9 + 8) * 8192;
        for (int i = threadIdx.x; i < 2048; i += 256) {
            int r = i >> 4, c4 = i & 15;
            int row = mb * 128 + r, k = c4 * 4;
            float4 v = make_float4(0.f, 0.f, 0.f, 0.f);
            if (k < LZ) v = *(const float4*)(z + (size_t)row * LZ + k);
            uint32_t sw = SWZ((uint32_t)(r * 128 + c4 * 8));
            split_store((uint8_t*)(g_A1h + off), (uint8_t*)(g_A1l + off), sw, v);
            split_store((uint8_t*)(g_A2h + off), (uint8_t*)(g_A2l + off), sw, v);
        }
    }
}

// ---------------- gating logits + softmax over E=8 ----------------
__global__ void logits_softmax(const float* __restrict__ h2,
                               const float* __restrict__ gW3,
                               const float* __restrict__ gb3) {
    int tid = blockIdx.x * blockDim.x + threadIdx.x;
    int row = tid >> 3, e = tid & 7;
    if (row >= BB) return;
    float s = gb3[e];
    const float* hr = h2 + (size_t)row * GHD;
    const float* wr = gW3 + (size_t)e * GHD;
#pragma unroll 8
    for (int i = 0; i < GHD; i++) s += hr[i] * wr[i];
    float m = s;
#pragma unroll
    for (int o = 4; o; o >>= 1) m = fmaxf(m, __shfl_xor_sync(0xffffffffu, m, o));
    float ex = expf(s - m);
    float sum = ex;
#pragma unroll
    for (int o = 4; o; o >>= 1) sum += __shfl_xor_sync(0xffffffffu, sum, o);
    g_gate[tid] = ex / sum;
}

// ---------------- host ----------------
extern "C" void kernel_launch(void* const* d_in, const int* in_sizes, int n_in,
                              void* d_out, int out_size) {
    const float* x   = (const float*)d_in[0];
    const float* z   = (const float*)d_in[1];
    const float* W0  = (const float*)d_in[2];
    const float* b0  = (const float*)d_in[3];
    const float* W1  = (const float*)d_in[4];
    const float* b1  = (const float*)d_in[5];
    const float* W2  = (const float*)d_in[6];
    const float* b2  = (const float*)d_in[7];
    const float* W3  = (const float*)d_in[8];
    const float* b3  = (const float*)d_in[9];
    const float* gW1 = (const float*)d_in[10];
    const float* gb1 = (const float*)d_in[11];
    const float* gW2 = (const float*)d_in[12];
    const float* gb2 = (const float*)d_in[13];
    const float* gW3 = (const float*)d_in[14];
    const float* gb3 = (const float*)d_in[15];
    float* out = (float*)d_out;
    (void)in_sizes; (void)n_in; (void)out_size;

    __half *A0h,*A0l,*A1h,*A1l,*A2h,*A2l,*A3h,*A3l,*G1h,*G1l;
    __half *pW0h,*pW0l,*pW1h,*pW1l,*pW2h,*pW2l,*pW3h,*pW3l,*pg1h,*pg1l,*pg2h,*pg2l;
    float *gh2, *gate;
    cudaGetSymbolAddress((void**)&A0h, g_A0h); cudaGetSymbolAddress((void**)&A0l, g_A0l);
    cudaGetSymbolAddress((void**)&A1h, g_A1h); cudaGetSymbolAddress((void**)&A1l, g_A1l);
    cudaGetSymbolAddress((void**)&A2h, g_A2h); cudaGetSymbolAddress((void**)&A2l, g_A2l);
    cudaGetSymbolAddress((void**)&A3h, g_A3h); cudaGetSymbolAddress((void**)&A3l, g_A3l);
    cudaGetSymbolAddress((void**)&G1h, g_G1h); cudaGetSymbolAddress((void**)&G1l, g_G1l);
    cudaGetSymbolAddress((void**)&pW0h, g_W0h); cudaGetSymbolAddress((void**)&pW0l, g_W0l);
    cudaGetSymbolAddress((void**)&pW1h, g_W1h); cudaGetSymbolAddress((void**)&pW1l, g_W1l);
    cudaGetSymbolAddress((void**)&pW2h, g_W2h); cudaGetSymbolAddress((void**)&pW2l, g_W2l);
    cudaGetSymbolAddress((void**)&pW3h, g_W3h); cudaGetSymbolAddress((void**)&pW3l, g_W3l);
    cudaGetSymbolAddress((void**)&pg1h, g_gW1h); cudaGetSymbolAddress((void**)&pg1l, g_gW1l);
    cudaGetSymbolAddress((void**)&pg2h, g_gW2h); cudaGetSymbolAddress((void**)&pg2l, g_gW2l);
    cudaGetSymbolAddress((void**)&gh2, g_gh2); cudaGetSymbolAddress((void**)&gate, g_gate);

    cudaFuncSetAttribute(moe_gemm<1,false,true,false>, cudaFuncAttributeMaxDynamicSharedMemorySize, SMEM_BYTES);
    cudaFuncSetAttribute(moe_gemm<1,false,true,true>,  cudaFuncAttributeMaxDynamicSharedMemorySize, SMEM_BYTES);
    cudaFuncSetAttribute(moe_gemm<8,true,true,false>,  cudaFuncAttributeMaxDynamicSharedMemorySize, SMEM_BYTES);
    cudaFuncSetAttribute(moe_gemm<8,true,false,true>,  cudaFuncAttributeMaxDynamicSharedMemorySize, SMEM_BYTES);

    // prepack weights (one launch) + inputs (one launch)
    PWJobs jobs;
    jobs.j[0] = {W0,  pW0h, pW0l, HH,  320, 8, 5, 0,    320};
    jobs.j[1] = {W1,  pW1h, pW1l, HH,  544, 8, 9, 320,  576};
    jobs.j[2] = {W2,  pW2h, pW2l, HH,  544, 8, 9, 896,  576};
    jobs.j[3] = {W3,  pW3h, pW3l, OO,  512, 2, 8, 1472, 128};
    jobs.j[4] = {gW1, pg1h, pg1l, GHD, 320, 2, 5, 1600, 10};
    jobs.j[5] = {gW2, pg2h, pg2l, GHD, GHD, 2, 2, 1610, 4};
    prepack_w_all<<<1614, 256>>>(jobs);
    prepack_a_all<<<MBK*5 + MBK, 256>>>(x, z);

    // gating MLP on tensor cores
    moe_gemm<1,false,true,false><<<dim3(2, MBK), NTHREADS, SMEM_BYTES>>>(
        A0h, A0l, 5, pg1h, pg1l, 2, gb1, nullptr, GHD, G1h, G1l, 2, nullptr, 0);
    moe_gemm<1,false,true,true><<<dim3(2, MBK), NTHREADS, SMEM_BYTES>>>(
        G1h, G1l, 2, pg2h, pg2l, 2, gb2, nullptr, GHD, nullptr, nullptr, 0, gh2, GHD);
    logits_softmax<<<BB*EE/256, 256>>>(gh2, gW3, gb3);

    // blended expert layers
    moe_gemm<8,true,true,false><<<dim3(8, MBK), NTHREADS, SMEM_BYTES>>>(
        A0h, A0l, 5, pW0h, pW0l, 8, b0, gate, HH, A1h, A1l, 9, nullptr, 0);
    moe_gemm<8,true,true,false><<<dim3(8, MBK), NTHREADS, SMEM_BYTES>>>(
        A1h, A1l, 9, pW1h, pW1l, 8, b1, gate, HH, A2h, A2l, 9, nullptr, 0);
    moe_gemm<8,true,true,false><<<dim3(8, MBK), NTHREADS, SMEM_BYTES>>>(
        A2h, A2l, 9, pW2h, pW2l, 8, b2, gate, HH, A3h, A3l, 8, nullptr, 0);
    moe_gemm<8,true,false,true><<<dim3(2, MBK), NTHREADS, SMEM_BYTES>>>(
        A3h, A3l, 8, pW3h, pW3l, 2, b3, gate, OO, nullptr, nullptr, 0, out, OO);
}